// round 4
// baseline (speedup 1.0000x reference)
#include <cuda_runtime.h>
#include <cuda_bf16.h>
#include <math.h>
#include <cstdint>

// Problem constants
constexpr int BB  = 64;      // batch
constexpr int LL  = 2048;    // sequence length
constexpr int DD  = 256;     // channels H
constexpr int NN2 = 32;      // diagonal modes
constexpr int MM  = BB * LL; // 131072 positions

typedef unsigned long long u64;

// ---------------- scratch (__device__ globals; no allocation allowed) --------
__device__ __align__(128) float4 g_wpk[2 * DD * (NN2 / 2)];
__device__ __align__(128) float4 g_cpk[2 * DD * (NN2 / 2)];
__device__ __align__(128) __nv_bfloat16 g_yh[(size_t)2 * MM * DD];   // 134 MB
__device__ __align__(128) __nv_bfloat16 g_yl[(size_t)2 * MM * DD];   // 134 MB
__device__ __align__(128) __nv_bfloat16 g_wbh[2 * 2 * DD * DD];      // reordered W hi
__device__ __align__(128) __nv_bfloat16 g_wbl[2 * 2 * DD * DD];      // reordered W lo
__device__ __align__(128) float g_bias2[2 * 2 * DD];                 // reordered bias

// ---------------- packed f32x2 helpers ---------------------------------------
__device__ __forceinline__ u64 pk2(float lo, float hi) {
    u64 r; asm("mov.b64 %0, {%1,%2};" : "=l"(r) : "f"(lo), "f"(hi)); return r;
}
__device__ __forceinline__ void upk2(u64 v, float& lo, float& hi) {
    asm("mov.b64 {%0,%1}, %2;" : "=f"(lo), "=f"(hi) : "l"(v));
}
__device__ __forceinline__ u64 fma2(u64 a, u64 b, u64 c) {
    u64 d; asm("fma.rn.f32x2 %0, %1, %2, %3;" : "=l"(d) : "l"(a), "l"(b), "l"(c)); return d;
}
__device__ __forceinline__ u64 mul2(u64 a, u64 b) {
    u64 d; asm("mul.rn.f32x2 %0, %1, %2;" : "=l"(d) : "l"(a), "l"(b)); return d;
}
__device__ __forceinline__ float gelu_exact(float v) {
    return 0.5f * v * (1.0f + erff(v * 0.70710678118654752f));
}
__device__ __forceinline__ float sigm(float v) {
    return 1.0f / (1.0f + expf(-v));
}

// ---------------- smem / async helpers ----------------------------------------
__device__ __forceinline__ uint32_t smem_u32(const void* p) {
    uint32_t a;
    asm("{ .reg .u64 t; cvta.to.shared.u64 t, %1; cvt.u32.u64 %0, t; }" : "=r"(a) : "l"(p));
    return a;
}
__device__ __forceinline__ uint32_t swz(uint32_t o) { return o ^ ((o >> 3) & 0x70); }

__device__ __forceinline__ void cpa16(uint32_t dst, const void* src) {
    asm volatile("cp.async.cg.shared.global [%0], [%1], 16;" :: "r"(dst), "l"(src));
}

#define LDM4(r, addr) \
    asm volatile("ldmatrix.sync.aligned.m8n8.x4.shared.b16 {%0,%1,%2,%3}, [%4];" \
        : "=r"((r)[0]), "=r"((r)[1]), "=r"((r)[2]), "=r"((r)[3]) : "r"(addr))

#define MMA16816(c, a, b0, b1) \
    asm volatile("mma.sync.aligned.m16n8k16.row.col.f32.bf16.bf16.f32 " \
        "{%0,%1,%2,%3}, {%4,%5,%6,%7}, {%8,%9}, {%0,%1,%2,%3};" \
        : "+f"((c)[0]), "+f"((c)[1]), "+f"((c)[2]), "+f"((c)[3]) \
        : "r"((a)[0]), "r"((a)[1]), "r"((a)[2]), "r"((a)[3]), "r"(b0), "r"(b1))

// ---------------- kernel 1: precompute discrete-time constants ---------------
__global__ void k_prep(const float* __restrict__ ld0,  const float* __restrict__ cre0,
                       const float* __restrict__ cim0, const float* __restrict__ lar0,
                       const float* __restrict__ aim0,
                       const float* __restrict__ ld1,  const float* __restrict__ cre1,
                       const float* __restrict__ cim1, const float* __restrict__ lar1,
                       const float* __restrict__ aim1)
{
    int i = blockIdx.x * blockDim.x + threadIdx.x;
    if (i >= 2 * DD * NN2) return;
    int d = i / (DD * NN2);
    int r = i % (DD * NN2);
    int h = r / NN2, n = r % NN2;
    const float* ld  = d ? ld1  : ld0;
    const float* cre = d ? cre1 : cre0;
    const float* cim = d ? cim1 : cim0;
    const float* lar = d ? lar1 : lar0;
    const float* aim = d ? aim1 : aim0;

    double dt  = exp((double)ld[h]);
    double Are = -exp((double)lar[h * NN2 + n]);
    double Aim = (double)aim[h * NN2 + n];
    double dre = Are * dt, dim_ = Aim * dt;
    double er  = exp(dre);
    double wr  = er * cos(dim_), wi = er * sin(dim_);
    double Er = wr - 1.0, Ei = wi;
    double den = Are * Are + Aim * Aim;
    double Fr = (Er * Are + Ei * Aim) / den;
    double Fi = (Ei * Are - Er * Aim) / den;
    double c0r = (double)cre[h * NN2 + n], c0i = (double)cim[h * NN2 + n];
    double Cr = 2.0 * (c0r * Fr - c0i * Fi);
    double Ci = 2.0 * (c0r * Fi + c0i * Fr);

    float* wp = (float*)g_wpk;
    float* cp = (float*)g_cpk;
    size_t base = ((size_t)(d * DD + h) * (NN2 / 2) + (n >> 1)) * 4;
    int comp = n & 1;
    wp[base + comp]     = (float)wr;
    wp[base + 2 + comp] = (float)wi;
    cp[base + comp]     = (float)Cr;
    cp[base + 2 + comp] = (float)Ci;
}

// ---------------- kernel 1b: reorder + bf16-split the GLU weights ------------
__global__ void k_wt(const float* __restrict__ w0, const float* __restrict__ w1,
                     const float* __restrict__ b0, const float* __restrict__ b1)
{
    int i = blockIdx.x * blockDim.x + threadIdx.x;
    if (i >= 2 * 2 * DD * DD) return;
    int d = i / (2 * DD * DD);
    int rem = i % (2 * DD * DD);
    int r = rem / DD, k = rem % DD;
    int o = (r & 1) ? (r >> 1) + DD : (r >> 1);
    const float* w = d ? w1 : w0;
    float v = w[(size_t)o * DD + k];
    __nv_bfloat16 hi = __float2bfloat16(v);
    float lof = v - __bfloat162float(hi);
    g_wbh[i] = hi;
    g_wbl[i] = __float2bfloat16(lof);
    if (k == 0) g_bias2[d * 2 * DD + r] = (d ? b1 : b0)[o];
}

// ---------------- kernel 2: diagonal SSM scan + D-skip + GELU ----------------
// Warp = 8 sequences x 4 lanes; lane holds 8 modes (4 f32x2 pairs).
// Block = 256 threads covers 64 channels of one (dir, batch); scans all L.
__global__ __launch_bounds__(256) void k_scan(const float* __restrict__ x,
                                              const float* __restrict__ ds0,
                                              const float* __restrict__ ds1)
{
    const int d  = blockIdx.z, b = blockIdx.y;
    const int h0 = blockIdx.x * 64;
    const int t  = threadIdx.x;
    const int w  = t >> 5, lane = t & 31;
    const int sq = lane >> 2, sub = lane & 3;
    const int ch = w * 8 + sq;
    const int h  = h0 + ch;

    const float4* wp = &g_wpk[(size_t)(d * DD + h) * (NN2 / 2) + sub * 4];
    const float4* cp = &g_cpk[(size_t)(d * DD + h) * (NN2 / 2) + sub * 4];
    u64 wr[4], wi[4], nwi[4], cr[4], nci[4], sr[4], si[4];
    #pragma unroll
    for (int p = 0; p < 4; p++) {
        float4 W = wp[p], C = cp[p];
        wr[p]  = pk2(W.x, W.y);
        wi[p]  = pk2(W.z, W.w);
        nwi[p] = pk2(-W.z, -W.w);
        cr[p]  = pk2(C.x, C.y);
        nci[p] = pk2(-C.z, -C.w);
        sr[p] = 0ull; si[p] = 0ull;
    }
    const float dsk = (d ? ds1 : ds0)[h];

    __shared__ __align__(16) float buf[64][64];
    const float* xb = x + (size_t)b * LL * DD;
    const size_t mbase = ((size_t)d * BB + b) * LL;

    for (int c = 0; c < LL / 64; c++) {
        // stage 64 steps x 64 channels (4 float4 per thread, coalesced)
        float4 v[4];
        #pragma unroll
        for (int j = 0; j < 4; j++) {
            int idx = t + 256 * j;
            int ir = idx >> 4, c4 = idx & 15;
            int rr = (d == 0) ? (c * 64 + ir) : (LL - 1 - c * 64 - ir);
            v[j] = *(const float4*)(xb + (size_t)rr * DD + h0 + c4 * 4);
        }
        __syncthreads();   // previous writeback done
        #pragma unroll
        for (int j = 0; j < 4; j++) {
            int idx = t + 256 * j;
            *(float4*)&buf[idx >> 4][(idx & 15) * 4] = v[j];
        }
        __syncthreads();

        // scan 64 steps
        #pragma unroll 4
        for (int i = 0; i < 64; i++) {
            float u = buf[i][ch];
            u64 u2 = pk2(u, u);
            u64 tt[4];
            #pragma unroll
            for (int p = 0; p < 4; p++) {
                tt[p] = mul2(wi[p], sr[p]);
                sr[p] = fma2(wr[p], sr[p], fma2(nwi[p], si[p], u2));
                si[p] = fma2(wr[p], si[p], tt[p]);
            }
            u64 acc = mul2(cr[0], sr[0]);
            acc = fma2(nci[0], si[0], acc);
            #pragma unroll
            for (int p = 1; p < 4; p++) {
                acc = fma2(cr[p], sr[p], acc);
                acc = fma2(nci[p], si[p], acc);
            }
            float lo, hi; upk2(acc, lo, hi);
            float rsum = lo + hi;
            rsum += __shfl_xor_sync(0xffffffffu, rsum, 1);
            rsum += __shfl_xor_sync(0xffffffffu, rsum, 2);
            if (sub == 0) buf[i][ch] = fmaf(dsk, u, rsum);
        }
        __syncthreads();

        // GELU + bf16 hi/lo split writeback
        #pragma unroll
        for (int j = 0; j < 4; j++) {
            int idx = t + 256 * j;
            int ir = idx >> 4, c4 = idx & 15;
            int rr = (d == 0) ? (c * 64 + ir) : (LL - 1 - c * 64 - ir);
            float4 vv = *(float4*)&buf[ir][c4 * 4];
            vv.x = gelu_exact(vv.x); vv.y = gelu_exact(vv.y);
            vv.z = gelu_exact(vv.z); vv.w = gelu_exact(vv.w);
            __nv_bfloat162 h01 = __floats2bfloat162_rn(vv.x, vv.y);
            __nv_bfloat162 h23 = __floats2bfloat162_rn(vv.z, vv.w);
            float2 f01 = __bfloat1622float2(h01);
            float2 f23 = __bfloat1622float2(h23);
            __nv_bfloat162 l01 = __floats2bfloat162_rn(vv.x - f01.x, vv.y - f01.y);
            __nv_bfloat162 l23 = __floats2bfloat162_rn(vv.z - f23.x, vv.w - f23.y);
            size_t base = (mbase + rr) * DD + h0 + c4 * 4;
            uint2 uh, ul;
            uh.x = *(uint32_t*)&h01; uh.y = *(uint32_t*)&h23;
            ul.x = *(uint32_t*)&l01; ul.y = *(uint32_t*)&l23;
            *(uint2*)&g_yh[base] = uh;
            *(uint2*)&g_yl[base] = ul;
        }
    }
}

// ---------------- kernel 3: mma.sync bf16-split GEMM + fused GLU epilogue ----
// CTA: 128(M) x 128(N); 8 warps of 64x32; 24 chunks (12 per dir) of K=64 in one
// continuous 4-stage cp.async pipeline; single barrier per chunk.
static constexpr int STAGE_BYTES = 32768;          // 16KB A + 16KB B
static constexpr int N_STAGE     = 4;
static constexpr int SM_TOTAL    = N_STAGE * STAGE_BYTES; // 128KB

__device__ __forceinline__ void load_chunk(uint32_t stage_base, int cc,
                                           size_t m0, int n0, int t)
{
    const int dir = cc / 12, c = cc % 12;
    const __nv_bfloat16* ya = (c < 8) ? g_yh : g_yl;
    const __nv_bfloat16* asrc = ya + ((size_t)dir * MM + m0) * DD + (c & 3) * 64;
    #pragma unroll
    for (int j = 0; j < 4; j++) {
        int idx = t + 256 * j;
        int row = idx >> 3, seg = idx & 7;
        cpa16(stage_base + swz(row * 128 + seg * 16), asrc + (size_t)row * DD + seg * 8);
    }
    const __nv_bfloat16* wb = (((c >> 2) & 3) == 1) ? g_wbl : g_wbh;
    const __nv_bfloat16* bsrc = wb + (size_t)dir * 2 * DD * DD + (size_t)n0 * DD + (c & 3) * 64;
    #pragma unroll
    for (int j = 0; j < 4; j++) {
        int idx = t + 256 * j;
        int row = idx >> 3, seg = idx & 7;
        cpa16(stage_base + 16384 + swz(row * 128 + seg * 16), bsrc + (size_t)row * DD + seg * 8);
    }
    asm volatile("cp.async.commit_group;" ::: "memory");
}

__global__ __launch_bounds__(256, 1) void k_mm2(float* __restrict__ out)
{
    extern __shared__ __align__(1024) char smem[];
    uint32_t sb = smem_u32(smem);
    const int t = threadIdx.x;
    const int lane = t & 31, w = t >> 5;
    const int mw = (w >> 2) * 64, nw = (w & 3) * 32;
    const int n0 = blockIdx.x * 128;
    const size_t m0 = (size_t)blockIdx.y * 128;

    const uint32_t xorv = (lane & 7) * 16;
    uint32_t relA[4], relB[2];
    #pragma unroll
    for (int i = 0; i < 4; i++)
        relA[i] = (uint32_t)(mw + i * 16 + (lane & 15)) * 128;
    #pragma unroll
    for (int p = 0; p < 2; p++)
        relB[p] = 16384u + (uint32_t)(nw + p * 16 + ((lane >> 4) << 3) + (lane & 7)) * 128;
    const uint32_t hsegA = (uint32_t)(lane >> 4);
    const uint32_t hsegB = (uint32_t)((lane >> 3) & 1);

    float acc[4][4][4];
    float oacc[4][4][2];
    #pragma unroll
    for (int i = 0; i < 4; i++)
        #pragma unroll
        for (int j = 0; j < 4; j++) {
            oacc[i][j][0] = 0.f; oacc[i][j][1] = 0.f;
            #pragma unroll
            for (int q = 0; q < 4; q++) acc[i][j][q] = 0.f;
        }

    load_chunk(sb + 0 * STAGE_BYTES, 0, m0, n0, t);
    load_chunk(sb + 1 * STAGE_BYTES, 1, m0, n0, t);
    load_chunk(sb + 2 * STAGE_BYTES, 2, m0, n0, t);

    for (int cc = 0; cc < 24; cc++) {
        if (cc <= 21)      asm volatile("cp.async.wait_group 2;" ::: "memory");
        else if (cc == 22) asm volatile("cp.async.wait_group 1;" ::: "memory");
        else               asm volatile("cp.async.wait_group 0;" ::: "memory");
        __syncthreads();

        // refill the stage consumed at chunk cc-1 (all threads passed that point)
        if (cc + 3 < 24) load_chunk(sb + (uint32_t)((cc + 3) & 3) * STAGE_BYTES,
                                    cc + 3, m0, n0, t);

        uint32_t base = sb + (uint32_t)(cc & 3) * STAGE_BYTES;
        #pragma unroll
        for (int kk = 0; kk < 4; kk++) {
            uint32_t soffA = (((uint32_t)(2 * kk) + hsegA) * 16) ^ xorv;
            uint32_t soffB = (((uint32_t)(2 * kk) + hsegB) * 16) ^ xorv;
            uint32_t afr[4][4], bfr[2][4];
            #pragma unroll
            for (int i = 0; i < 4; i++) LDM4(afr[i], base + relA[i] + soffA);
            #pragma unroll
            for (int p = 0; p < 2; p++) LDM4(bfr[p], base + relB[p] + soffB);
            #pragma unroll
            for (int i = 0; i < 4; i++)
                #pragma unroll
                for (int j = 0; j < 4; j++)
                    MMA16816(acc[i][j], afr[i], bfr[j >> 1][(j & 1) * 2],
                             bfr[j >> 1][(j & 1) * 2 + 1]);
        }

        if (cc == 11 || cc == 23) {
            // fused GLU fold for this dir (columns interleaved: even=lin, odd=gate)
            int dir = cc / 12;
            #pragma unroll
            for (int i = 0; i < 4; i++)
                #pragma unroll
                for (int j = 0; j < 4; j++) {
                    int nl = nw + 8 * j + 2 * (lane & 3);
                    float bl = g_bias2[dir * 512 + n0 + nl];
                    float bg = g_bias2[dir * 512 + n0 + nl + 1];
                    oacc[i][j][0] += (acc[i][j][0] + bl) * sigm(acc[i][j][1] + bg);
                    oacc[i][j][1] += (acc[i][j][2] + bl) * sigm(acc[i][j][3] + bg);
                    #pragma unroll
                    for (int q = 0; q < 4; q++) acc[i][j][q] = 0.f;
                }
        }
    }

    const int q = lane >> 2;
    const int chb = (n0 + nw) / 2 + (lane & 3);
    #pragma unroll
    for (int i = 0; i < 4; i++)
        #pragma unroll
        for (int s = 0; s < 2; s++) {
            size_t m = m0 + mw + 16 * i + q + 8 * s;
            float* dst = out + m * DD + chb;
            #pragma unroll
            for (int j = 0; j < 4; j++) dst[4 * j] = oacc[i][j][s];
        }
}

// ---------------- launch ------------------------------------------------------
extern "C" void kernel_launch(void* const* d_in, const int* in_sizes, int n_in,
                              void* d_out, int out_size)
{
    const float* x    = (const float*)d_in[0];
    const float* ld0  = (const float*)d_in[1];
    const float* cre0 = (const float*)d_in[2];
    const float* cim0 = (const float*)d_in[3];
    const float* lar0 = (const float*)d_in[4];
    const float* aim0 = (const float*)d_in[5];
    const float* ds0  = (const float*)d_in[6];
    const float* wg0  = (const float*)d_in[7];
    const float* bg0  = (const float*)d_in[8];
    const float* ld1  = (const float*)d_in[9];
    const float* cre1 = (const float*)d_in[10];
    const float* cim1 = (const float*)d_in[11];
    const float* lar1 = (const float*)d_in[12];
    const float* aim1 = (const float*)d_in[13];
    const float* ds1  = (const float*)d_in[14];
    const float* wg1  = (const float*)d_in[15];
    const float* bg1  = (const float*)d_in[16];
    float* out = (float*)d_out;

    static bool attr_done = false;
    if (!attr_done) {
        cudaFuncSetAttribute(k_mm2, cudaFuncAttributeMaxDynamicSharedMemorySize, SM_TOTAL);
        attr_done = true;
    }

    k_prep<<<(2 * DD * NN2 + 255) / 256, 256>>>(ld0, cre0, cim0, lar0, aim0,
                                                ld1, cre1, cim1, lar1, aim1);
    k_wt<<<(2 * 2 * DD * DD + 255) / 256, 256>>>(wg0, wg1, bg0, bg1);
    k_scan<<<dim3(DD / 64, BB, 2), 256>>>(x, ds0, ds1);
    k_mm2<<<dim3(4, MM / 128), 256, SM_TOTAL>>>(out);
}

// round 5
// speedup vs baseline: 1.3257x; 1.3257x over previous
#include <cuda_runtime.h>
#include <cuda_fp16.h>
#include <math.h>
#include <cstdint>

// Problem constants
constexpr int BB  = 64;      // batch
constexpr int LL  = 2048;    // sequence length
constexpr int DD  = 256;     // channels H
constexpr int NN2 = 32;      // diagonal modes
constexpr int MM  = BB * LL; // 131072 positions

typedef unsigned long long u64;

// ---------------- scratch (__device__ globals; no allocation allowed) --------
__device__ __align__(128) float4 g_wpk[2 * DD * (NN2 / 2)];
__device__ __align__(128) float4 g_cpk[2 * DD * (NN2 / 2)];
__device__ __align__(128) __half g_y[(size_t)2 * MM * DD];     // 134 MB (fp16 GELU(y))
__device__ __align__(128) __half g_wh[2 * 2 * DD * DD];        // reordered W (fp16)
__device__ __align__(128) float  g_bias2[2 * 2 * DD];          // reordered bias

// ---------------- packed f32x2 helpers ---------------------------------------
__device__ __forceinline__ u64 pk2(float lo, float hi) {
    u64 r; asm("mov.b64 %0, {%1,%2};" : "=l"(r) : "f"(lo), "f"(hi)); return r;
}
__device__ __forceinline__ void upk2(u64 v, float& lo, float& hi) {
    asm("mov.b64 {%0,%1}, %2;" : "=f"(lo), "=f"(hi) : "l"(v));
}
__device__ __forceinline__ u64 fma2(u64 a, u64 b, u64 c) {
    u64 d; asm("fma.rn.f32x2 %0, %1, %2, %3;" : "=l"(d) : "l"(a), "l"(b), "l"(c)); return d;
}
__device__ __forceinline__ u64 mul2(u64 a, u64 b) {
    u64 d; asm("mul.rn.f32x2 %0, %1, %2;" : "=l"(d) : "l"(a), "l"(b)); return d;
}
__device__ __forceinline__ float gelu_exact(float v) {
    return 0.5f * v * (1.0f + erff(v * 0.70710678118654752f));
}
__device__ __forceinline__ float sigm(float v) {
    return 1.0f / (1.0f + expf(-v));
}

// ---------------- smem / async helpers ----------------------------------------
__device__ __forceinline__ uint32_t smem_u32(const void* p) {
    uint32_t a;
    asm("{ .reg .u64 t; cvta.to.shared.u64 t, %1; cvt.u32.u64 %0, t; }" : "=r"(a) : "l"(p));
    return a;
}
__device__ __forceinline__ uint32_t swz(uint32_t o) { return o ^ ((o >> 3) & 0x70); }

__device__ __forceinline__ void cpa16(uint32_t dst, const void* src) {
    asm volatile("cp.async.cg.shared.global [%0], [%1], 16;" :: "r"(dst), "l"(src));
}

#define LDM4(r, addr) \
    asm volatile("ldmatrix.sync.aligned.m8n8.x4.shared.b16 {%0,%1,%2,%3}, [%4];" \
        : "=r"((r)[0]), "=r"((r)[1]), "=r"((r)[2]), "=r"((r)[3]) : "r"(addr))

#define MMA16816(c, a, b0, b1) \
    asm volatile("mma.sync.aligned.m16n8k16.row.col.f32.f16.f16.f32 " \
        "{%0,%1,%2,%3}, {%4,%5,%6,%7}, {%8,%9}, {%0,%1,%2,%3};" \
        : "+f"((c)[0]), "+f"((c)[1]), "+f"((c)[2]), "+f"((c)[3]) \
        : "r"((a)[0]), "r"((a)[1]), "r"((a)[2]), "r"((a)[3]), "r"(b0), "r"(b1))

// ---------------- kernel 1: precompute discrete-time constants ---------------
__global__ void k_prep(const float* __restrict__ ld0,  const float* __restrict__ cre0,
                       const float* __restrict__ cim0, const float* __restrict__ lar0,
                       const float* __restrict__ aim0,
                       const float* __restrict__ ld1,  const float* __restrict__ cre1,
                       const float* __restrict__ cim1, const float* __restrict__ lar1,
                       const float* __restrict__ aim1)
{
    int i = blockIdx.x * blockDim.x + threadIdx.x;
    if (i >= 2 * DD * NN2) return;
    int d = i / (DD * NN2);
    int r = i % (DD * NN2);
    int h = r / NN2, n = r % NN2;
    const float* ld  = d ? ld1  : ld0;
    const float* cre = d ? cre1 : cre0;
    const float* cim = d ? cim1 : cim0;
    const float* lar = d ? lar1 : lar0;
    const float* aim = d ? aim1 : aim0;

    double dt  = exp((double)ld[h]);
    double Are = -exp((double)lar[h * NN2 + n]);
    double Aim = (double)aim[h * NN2 + n];
    double dre = Are * dt, dim_ = Aim * dt;
    double er  = exp(dre);
    double wr  = er * cos(dim_), wi = er * sin(dim_);
    double Er = wr - 1.0, Ei = wi;
    double den = Are * Are + Aim * Aim;
    double Fr = (Er * Are + Ei * Aim) / den;
    double Fi = (Ei * Are - Er * Aim) / den;
    double c0r = (double)cre[h * NN2 + n], c0i = (double)cim[h * NN2 + n];
    double Cr = 2.0 * (c0r * Fr - c0i * Fi);
    double Ci = 2.0 * (c0r * Fi + c0i * Fr);

    float* wp = (float*)g_wpk;
    float* cp = (float*)g_cpk;
    size_t base = ((size_t)(d * DD + h) * (NN2 / 2) + (n >> 1)) * 4;
    int comp = n & 1;
    wp[base + comp]     = (float)wr;
    wp[base + 2 + comp] = (float)wi;
    cp[base + comp]     = (float)Cr;
    cp[base + 2 + comp] = (float)Ci;
}

// ---------------- kernel 1b: reorder + fp16 GLU weights ----------------------
// New row r: r=2j -> orig row j (linear); r=2j+1 -> orig row j+256 (gate)
__global__ void k_wt(const float* __restrict__ w0, const float* __restrict__ w1,
                     const float* __restrict__ b0, const float* __restrict__ b1)
{
    int i = blockIdx.x * blockDim.x + threadIdx.x;
    if (i >= 2 * 2 * DD * DD) return;
    int d = i / (2 * DD * DD);
    int rem = i % (2 * DD * DD);
    int r = rem / DD, k = rem % DD;
    int o = (r & 1) ? (r >> 1) + DD : (r >> 1);
    const float* w = d ? w1 : w0;
    g_wh[i] = __float2half_rn(w[(size_t)o * DD + k]);
    if (k == 0) g_bias2[d * 2 * DD + r] = (d ? b1 : b0)[o];
}

// ---------------- kernel 2: diagonal SSM scan + D-skip + GELU ----------------
// Warp = 8 sequences x 4 lanes; lane holds 8 modes (4 f32x2 pairs).
__global__ __launch_bounds__(256) void k_scan(const float* __restrict__ x,
                                              const float* __restrict__ ds0,
                                              const float* __restrict__ ds1)
{
    const int d  = blockIdx.z, b = blockIdx.y;
    const int h0 = blockIdx.x * 64;
    const int t  = threadIdx.x;
    const int w  = t >> 5, lane = t & 31;
    const int sq = lane >> 2, sub = lane & 3;
    const int ch = w * 8 + sq;
    const int h  = h0 + ch;

    const float4* wp = &g_wpk[(size_t)(d * DD + h) * (NN2 / 2) + sub * 4];
    const float4* cp = &g_cpk[(size_t)(d * DD + h) * (NN2 / 2) + sub * 4];
    u64 wr[4], wi[4], nwi[4], cr[4], nci[4], sr[4], si[4];
    #pragma unroll
    for (int p = 0; p < 4; p++) {
        float4 W = wp[p], C = cp[p];
        wr[p]  = pk2(W.x, W.y);
        wi[p]  = pk2(W.z, W.w);
        nwi[p] = pk2(-W.z, -W.w);
        cr[p]  = pk2(C.x, C.y);
        nci[p] = pk2(-C.z, -C.w);
        sr[p] = 0ull; si[p] = 0ull;
    }
    const float dsk = (d ? ds1 : ds0)[h];

    __shared__ __align__(16) float buf[64][64];
    const float* xb = x + (size_t)b * LL * DD;
    const size_t mbase = ((size_t)d * BB + b) * LL;

    for (int c = 0; c < LL / 64; c++) {
        float4 v[4];
        #pragma unroll
        for (int j = 0; j < 4; j++) {
            int idx = t + 256 * j;
            int ir = idx >> 4, c4 = idx & 15;
            int rr = (d == 0) ? (c * 64 + ir) : (LL - 1 - c * 64 - ir);
            v[j] = *(const float4*)(xb + (size_t)rr * DD + h0 + c4 * 4);
        }
        __syncthreads();
        #pragma unroll
        for (int j = 0; j < 4; j++) {
            int idx = t + 256 * j;
            *(float4*)&buf[idx >> 4][(idx & 15) * 4] = v[j];
        }
        __syncthreads();

        #pragma unroll 4
        for (int i = 0; i < 64; i++) {
            float u = buf[i][ch];
            u64 u2 = pk2(u, u);
            u64 tt[4];
            #pragma unroll
            for (int p = 0; p < 4; p++) {
                tt[p] = mul2(wi[p], sr[p]);
                sr[p] = fma2(wr[p], sr[p], fma2(nwi[p], si[p], u2));
                si[p] = fma2(wr[p], si[p], tt[p]);
            }
            u64 acc = mul2(cr[0], sr[0]);
            acc = fma2(nci[0], si[0], acc);
            #pragma unroll
            for (int p = 1; p < 4; p++) {
                acc = fma2(cr[p], sr[p], acc);
                acc = fma2(nci[p], si[p], acc);
            }
            float lo, hi; upk2(acc, lo, hi);
            float rsum = lo + hi;
            rsum += __shfl_xor_sync(0xffffffffu, rsum, 1);
            rsum += __shfl_xor_sync(0xffffffffu, rsum, 2);
            if (sub == 0) buf[i][ch] = fmaf(dsk, u, rsum);
        }
        __syncthreads();

        // GELU + fp16 writeback
        #pragma unroll
        for (int j = 0; j < 4; j++) {
            int idx = t + 256 * j;
            int ir = idx >> 4, c4 = idx & 15;
            int rr = (d == 0) ? (c * 64 + ir) : (LL - 1 - c * 64 - ir);
            float4 vv = *(float4*)&buf[ir][c4 * 4];
            vv.x = gelu_exact(vv.x); vv.y = gelu_exact(vv.y);
            vv.z = gelu_exact(vv.z); vv.w = gelu_exact(vv.w);
            __half2 h01 = __floats2half2_rn(vv.x, vv.y);
            __half2 h23 = __floats2half2_rn(vv.z, vv.w);
            size_t base = (mbase + rr) * DD + h0 + c4 * 4;
            uint2 uo;
            uo.x = *(uint32_t*)&h01; uo.y = *(uint32_t*)&h23;
            *(uint2*)&g_y[base] = uo;
        }
    }
}

// ---------------- kernel 3: fp16 mma GEMM, A-resident, fused GLU -------------
// CTA = one 128-row M tile. A (both dirs, K=256, fp16) = 128KB resident smem.
// Loop over 32 chunks g = (n0[4] x dir[2] x c[4]); B chunk = 128N x 64K = 16KB
// streamed through a 4-stage ring (64KB). GLU fold at c==3; store at dir==1.
static constexpr int A_BYTES   = 2 * 4 * 16384;            // 128KB (8 planes)
static constexpr int B_STAGE   = 16384;
static constexpr int SM_TOTAL  = A_BYTES + 4 * B_STAGE;    // 192KB

__device__ __forceinline__ void load_A(uint32_t sb, size_t m0, int t)
{
    #pragma unroll
    for (int j = 0; j < 32; j++) {
        int idx = t + 256 * j;
        int plane = idx >> 10;            // dir*4 + c
        int r = (idx >> 3) & 127, seg = idx & 7;
        int dir = plane >> 2, c = plane & 3;
        const __half* src = g_y + ((size_t)dir * MM + m0 + r) * DD + c * 64 + seg * 8;
        cpa16(sb + plane * 16384 + swz(r * 128 + seg * 16), src);
    }
}

__device__ __forceinline__ void load_B(uint32_t bbase, int g, int t)
{
    const int n0 = g >> 3, dir = (g >> 2) & 1, c = g & 3;
    const __half* bsrc = g_wh + (size_t)dir * 2 * DD * DD
                       + (size_t)(n0 * 128) * DD + c * 64;
    #pragma unroll
    for (int j = 0; j < 4; j++) {
        int idx = t + 256 * j;
        int r = idx >> 3, seg = idx & 7;
        cpa16(bbase + swz(r * 128 + seg * 16), bsrc + (size_t)r * DD + seg * 8);
    }
    asm volatile("cp.async.commit_group;" ::: "memory");
}

__global__ __launch_bounds__(256, 1) void k_mm2(float* __restrict__ out)
{
    extern __shared__ __align__(1024) char smem[];
    uint32_t sb = smem_u32(smem);
    const uint32_t bB = sb + A_BYTES;
    const int t = threadIdx.x;
    const int lane = t & 31, w = t >> 5;
    const int mw = (w >> 2) * 64, nw = (w & 3) * 32;
    const size_t m0 = (size_t)blockIdx.x * 128;

    const uint32_t xorv = (lane & 7) * 16;
    uint32_t relA[4], relB[2];
    #pragma unroll
    for (int i = 0; i < 4; i++)
        relA[i] = (uint32_t)(mw + i * 16 + (lane & 15)) * 128;
    #pragma unroll
    for (int p = 0; p < 2; p++)
        relB[p] = (uint32_t)(nw + p * 16 + ((lane >> 4) << 3) + (lane & 7)) * 128;
    const uint32_t hsegA = (uint32_t)(lane >> 4);
    const uint32_t hsegB = (uint32_t)((lane >> 3) & 1);

    float acc[4][4][4];
    float oacc[4][4][2];
    #pragma unroll
    for (int i = 0; i < 4; i++)
        #pragma unroll
        for (int j = 0; j < 4; j++) {
            oacc[i][j][0] = 0.f; oacc[i][j][1] = 0.f;
            #pragma unroll
            for (int q = 0; q < 4; q++) acc[i][j][q] = 0.f;
        }

    // prologue: A (both dirs) + B chunk 0 in group 0; B1, B2 own groups
    load_A(sb, m0, t);
    load_B(bB + 0 * B_STAGE, 0, t);
    load_B(bB + 1 * B_STAGE, 1, t);
    load_B(bB + 2 * B_STAGE, 2, t);

    for (int g = 0; g < 32; g++) {
        if (g <= 29)      asm volatile("cp.async.wait_group 2;" ::: "memory");
        else if (g == 30) asm volatile("cp.async.wait_group 1;" ::: "memory");
        else              asm volatile("cp.async.wait_group 0;" ::: "memory");
        __syncthreads();

        if (g + 3 < 32) load_B(bB + (uint32_t)((g + 3) & 3) * B_STAGE, g + 3, t);

        const int n0 = g >> 3, dir = (g >> 2) & 1, c = g & 3;
        const uint32_t abase = sb + (uint32_t)(dir * 4 + c) * 16384;
        const uint32_t bbase = bB + (uint32_t)(g & 3) * B_STAGE;

        #pragma unroll
        for (int kk = 0; kk < 4; kk++) {
            uint32_t soffA = (((uint32_t)(2 * kk) + hsegA) * 16) ^ xorv;
            uint32_t soffB = (((uint32_t)(2 * kk) + hsegB) * 16) ^ xorv;
            uint32_t afr[4][4], bfr[2][4];
            #pragma unroll
            for (int i = 0; i < 4; i++) LDM4(afr[i], abase + relA[i] + soffA);
            #pragma unroll
            for (int p = 0; p < 2; p++) LDM4(bfr[p], bbase + relB[p] + soffB);
            #pragma unroll
            for (int i = 0; i < 4; i++)
                #pragma unroll
                for (int j = 0; j < 4; j++)
                    MMA16816(acc[i][j], afr[i], bfr[j >> 1][(j & 1) * 2],
                             bfr[j >> 1][(j & 1) * 2 + 1]);
        }

        if (c == 3) {
            // GLU fold (cols interleaved: even=linear, odd=gate)
            #pragma unroll
            for (int i = 0; i < 4; i++)
                #pragma unroll
                for (int j = 0; j < 4; j++) {
                    int nl = n0 * 128 + nw + 8 * j + 2 * (lane & 3);
                    float bl = g_bias2[dir * 512 + nl];
                    float bg = g_bias2[dir * 512 + nl + 1];
                    oacc[i][j][0] += (acc[i][j][0] + bl) * sigm(acc[i][j][1] + bg);
                    oacc[i][j][1] += (acc[i][j][2] + bl) * sigm(acc[i][j][3] + bg);
                    #pragma unroll
                    for (int q = 0; q < 4; q++) acc[i][j][q] = 0.f;
                }
            if (dir == 1) {
                const int q = lane >> 2;
                const int chb = (n0 * 128 + nw) / 2 + (lane & 3);
                #pragma unroll
                for (int i = 0; i < 4; i++)
                    #pragma unroll
                    for (int s = 0; s < 2; s++) {
                        size_t m = m0 + mw + 16 * i + q + 8 * s;
                        float* dst = out + m * DD + chb;
                        #pragma unroll
                        for (int j = 0; j < 4; j++) dst[4 * j] = oacc[i][j][s];
                    }
                #pragma unroll
                for (int i = 0; i < 4; i++)
                    #pragma unroll
                    for (int j = 0; j < 4; j++) {
                        oacc[i][j][0] = 0.f; oacc[i][j][1] = 0.f;
                    }
            }
        }
    }
}

// ---------------- launch ------------------------------------------------------
extern "C" void kernel_launch(void* const* d_in, const int* in_sizes, int n_in,
                              void* d_out, int out_size)
{
    const float* x    = (const float*)d_in[0];
    const float* ld0  = (const float*)d_in[1];
    const float* cre0 = (const float*)d_in[2];
    const float* cim0 = (const float*)d_in[3];
    const float* lar0 = (const float*)d_in[4];
    const float* aim0 = (const float*)d_in[5];
    const float* ds0  = (const float*)d_in[6];
    const float* wg0  = (const float*)d_in[7];
    const float* bg0  = (const float*)d_in[8];
    const float* ld1  = (const float*)d_in[9];
    const float* cre1 = (const float*)d_in[10];
    const float* cim1 = (const float*)d_in[11];
    const float* lar1 = (const float*)d_in[12];
    const float* aim1 = (const float*)d_in[13];
    const float* ds1  = (const float*)d_in[14];
    const float* wg1  = (const float*)d_in[15];
    const float* bg1  = (const float*)d_in[16];
    float* out = (float*)d_out;

    static bool attr_done = false;
    if (!attr_done) {
        cudaFuncSetAttribute(k_mm2, cudaFuncAttributeMaxDynamicSharedMemorySize, SM_TOTAL);
        attr_done = true;
    }

    k_prep<<<(2 * DD * NN2 + 255) / 256, 256>>>(ld0, cre0, cim0, lar0, aim0,
                                                ld1, cre1, cim1, lar1, aim1);
    k_wt<<<(2 * 2 * DD * DD + 255) / 256, 256>>>(wg0, wg1, bg0, bg1);
    k_scan<<<dim3(DD / 64, BB, 2), 256>>>(x, ds0, ds1);
    k_mm2<<<MM / 128, 256, SM_TOTAL>>>(out);
}

// round 7
// speedup vs baseline: 1.4271x; 1.0765x over previous
#include <cuda_runtime.h>
#include <cuda_fp16.h>
#include <math.h>
#include <cstdint>

// Problem constants
constexpr int BB  = 64;      // batch
constexpr int LL  = 2048;    // sequence length
constexpr int DD  = 256;     // channels H
constexpr int NN2 = 32;      // diagonal modes
constexpr int MM  = BB * LL; // 131072 positions

typedef unsigned long long u64;

// ---------------- scratch (__device__ globals; no allocation allowed) --------
__device__ __align__(128) float4 g_wpk[2 * DD * (NN2 / 2)];
__device__ __align__(128) float4 g_cpk[2 * DD * (NN2 / 2)];
__device__ __align__(128) __half g_y[(size_t)2 * MM * DD];     // 134 MB (fp16 GELU(y))
__device__ __align__(128) __half g_wh[2 * 2 * DD * DD];        // reordered W (fp16)
__device__ __align__(128) float  g_bias2[2 * 2 * DD];          // reordered bias

// ---------------- packed f32x2 helpers ---------------------------------------
__device__ __forceinline__ u64 pk2(float lo, float hi) {
    u64 r; asm("mov.b64 %0, {%1,%2};" : "=l"(r) : "f"(lo), "f"(hi)); return r;
}
__device__ __forceinline__ void upk2(u64 v, float& lo, float& hi) {
    asm("mov.b64 {%0,%1}, %2;" : "=f"(lo), "=f"(hi) : "l"(v));
}
__device__ __forceinline__ u64 fma2(u64 a, u64 b, u64 c) {
    u64 d; asm("fma.rn.f32x2 %0, %1, %2, %3;" : "=l"(d) : "l"(a), "l"(b), "l"(c)); return d;
}
__device__ __forceinline__ u64 mul2(u64 a, u64 b) {
    u64 d; asm("mul.rn.f32x2 %0, %1, %2;" : "=l"(d) : "l"(a), "l"(b)); return d;
}
__device__ __forceinline__ float gelu_exact(float v) {
    return 0.5f * v * (1.0f + erff(v * 0.70710678118654752f));
}
__device__ __forceinline__ float sigm(float v) {
    return 1.0f / (1.0f + expf(-v));
}

// ---------------- smem / async helpers ----------------------------------------
__device__ __forceinline__ uint32_t smem_u32(const void* p) {
    uint32_t a;
    asm("{ .reg .u64 t; cvta.to.shared.u64 t, %1; cvt.u32.u64 %0, t; }" : "=r"(a) : "l"(p));
    return a;
}
__device__ __forceinline__ uint32_t swz(uint32_t o) { return o ^ ((o >> 3) & 0x70); }

__device__ __forceinline__ void cpa16(uint32_t dst, const void* src) {
    asm volatile("cp.async.cg.shared.global [%0], [%1], 16;" :: "r"(dst), "l"(src));
}

#define LDM4(r, addr) \
    asm volatile("ldmatrix.sync.aligned.m8n8.x4.shared.b16 {%0,%1,%2,%3}, [%4];" \
        : "=r"((r)[0]), "=r"((r)[1]), "=r"((r)[2]), "=r"((r)[3]) : "r"(addr))

#define MMA16816(c, a, b0, b1) \
    asm volatile("mma.sync.aligned.m16n8k16.row.col.f32.f16.f16.f32 " \
        "{%0,%1,%2,%3}, {%4,%5,%6,%7}, {%8,%9}, {%0,%1,%2,%3};" \
        : "+f"((c)[0]), "+f"((c)[1]), "+f"((c)[2]), "+f"((c)[3]) \
        : "r"((a)[0]), "r"((a)[1]), "r"((a)[2]), "r"((a)[3]), "r"(b0), "r"(b1))

// ---------------- kernel 1: precompute discrete-time constants ---------------
__global__ void k_prep(const float* __restrict__ ld0,  const float* __restrict__ cre0,
                       const float* __restrict__ cim0, const float* __restrict__ lar0,
                       const float* __restrict__ aim0,
                       const float* __restrict__ ld1,  const float* __restrict__ cre1,
                       const float* __restrict__ cim1, const float* __restrict__ lar1,
                       const float* __restrict__ aim1)
{
    int i = blockIdx.x * blockDim.x + threadIdx.x;
    if (i >= 2 * DD * NN2) return;
    int d = i / (DD * NN2);
    int r = i % (DD * NN2);
    int h = r / NN2, n = r % NN2;
    const float* ld  = d ? ld1  : ld0;
    const float* cre = d ? cre1 : cre0;
    const float* cim = d ? cim1 : cim0;
    const float* lar = d ? lar1 : lar0;
    const float* aim = d ? aim1 : aim0;

    double dt  = exp((double)ld[h]);
    double Are = -exp((double)lar[h * NN2 + n]);
    double Aim = (double)aim[h * NN2 + n];
    double dre = Are * dt, dim_ = Aim * dt;
    double er  = exp(dre);
    double wr  = er * cos(dim_), wi = er * sin(dim_);
    double Er = wr - 1.0, Ei = wi;
    double den = Are * Are + Aim * Aim;
    double Fr = (Er * Are + Ei * Aim) / den;
    double Fi = (Ei * Are - Er * Aim) / den;
    double c0r = (double)cre[h * NN2 + n], c0i = (double)cim[h * NN2 + n];
    double Cr = 2.0 * (c0r * Fr - c0i * Fi);
    double Ci = 2.0 * (c0r * Fi + c0i * Fr);

    float* wp = (float*)g_wpk;
    float* cp = (float*)g_cpk;
    size_t base = ((size_t)(d * DD + h) * (NN2 / 2) + (n >> 1)) * 4;
    int comp = n & 1;
    wp[base + comp]     = (float)wr;
    wp[base + 2 + comp] = (float)wi;
    cp[base + comp]     = (float)Cr;
    cp[base + 2 + comp] = (float)Ci;
}

// ---------------- kernel 1b: reorder + fp16 GLU weights ----------------------
__global__ void k_wt(const float* __restrict__ w0, const float* __restrict__ w1,
                     const float* __restrict__ b0, const float* __restrict__ b1)
{
    int i = blockIdx.x * blockDim.x + threadIdx.x;
    if (i >= 2 * 2 * DD * DD) return;
    int d = i / (2 * DD * DD);
    int rem = i % (2 * DD * DD);
    int r = rem / DD, k = rem % DD;
    int o = (r & 1) ? (r >> 1) + DD : (r >> 1);
    const float* w = d ? w1 : w0;
    g_wh[i] = __float2half_rn(w[(size_t)o * DD + k]);
    if (k == 0) g_bias2[d * 2 * DD + r] = (d ? b1 : b0)[o];
}

// ---------------- kernel 2: two-step diagonal SSM scan + D-skip + GELU -------
// Warp = 8 sequences x 4 lanes; lane holds 8 modes (4 f32x2 pairs).
// Two time-steps per iteration:
//   s_new = w^2 s + (w u0 + u1)
//   y[2i]   = Re(C w s_old) + (K0 + D) u0      (K0 = sum Re C)
//   y[2i+1] = Re(C s_new)   + D u1
__global__ __launch_bounds__(256) void k_scan(const float* __restrict__ x,
                                              const float* __restrict__ ds0,
                                              const float* __restrict__ ds1)
{
    const int d  = blockIdx.z, b = blockIdx.y;
    const int h0 = blockIdx.x * 64;
    const int t  = threadIdx.x;
    const int w  = t >> 5, lane = t & 31;
    const int sq = lane >> 2, sub = lane & 3;
    const int ch = w * 8 + sq;
    const int h  = h0 + ch;

    const float4* wp = &g_wpk[(size_t)(d * DD + h) * (NN2 / 2) + sub * 4];
    const float4* cp = &g_cpk[(size_t)(d * DD + h) * (NN2 / 2) + sub * 4];
    u64 wr[4], wi[4], w2r[4], w2i[4], nw2i[4], c1r[4], nc1i[4], cr[4], nci[4], sr[4], si[4];
    float k0 = 0.0f;
    #pragma unroll
    for (int p = 0; p < 4; p++) {
        float4 W = wp[p], C = cp[p];
        wr[p] = pk2(W.x, W.y);
        wi[p] = pk2(W.z, W.w);
        float w2rx = W.x * W.x - W.z * W.z, w2ry = W.y * W.y - W.w * W.w;
        float w2ix = 2.0f * W.x * W.z,      w2iy = 2.0f * W.y * W.w;
        w2r[p]  = pk2(w2rx, w2ry);
        w2i[p]  = pk2(w2ix, w2iy);
        nw2i[p] = pk2(-w2ix, -w2iy);
        float c1rx = C.x * W.x - C.z * W.z, c1ry = C.y * W.y - C.w * W.w;
        float c1ix = C.x * W.z + C.z * W.x, c1iy = C.y * W.w + C.w * W.y;
        c1r[p]  = pk2(c1rx, c1ry);
        nc1i[p] = pk2(-c1ix, -c1iy);
        cr[p]  = pk2(C.x, C.y);
        nci[p] = pk2(-C.z, -C.w);
        k0 += C.x + C.y;
        sr[p] = 0ull; si[p] = 0ull;
    }
    k0 += __shfl_xor_sync(0xffffffffu, k0, 1);
    k0 += __shfl_xor_sync(0xffffffffu, k0, 2);
    const float dsk = (d ? ds1 : ds0)[h];
    const float a0  = k0 + dsk;

    __shared__ __align__(16) float buf[64][64];
    const float* xb = x + (size_t)b * LL * DD;
    const size_t mbase = ((size_t)d * BB + b) * LL;

    for (int c = 0; c < LL / 64; c++) {
        float4 v[4];
        #pragma unroll
        for (int j = 0; j < 4; j++) {
            int idx = t + 256 * j;
            int ir = idx >> 4, c4 = idx & 15;
            int rr = (d == 0) ? (c * 64 + ir) : (LL - 1 - c * 64 - ir);
            v[j] = *(const float4*)(xb + (size_t)rr * DD + h0 + c4 * 4);
        }
        __syncthreads();
        #pragma unroll
        for (int j = 0; j < 4; j++) {
            int idx = t + 256 * j;
            *(float4*)&buf[idx >> 4][(idx & 15) * 4] = v[j];
        }
        __syncthreads();

        #pragma unroll 4
        for (int i2 = 0; i2 < 32; i2++) {
            float u0 = buf[2 * i2][ch], u1 = buf[2 * i2 + 1][ch];
            u64 ub0 = pk2(u0, u0), ub1 = pk2(u1, u1);

            // output 1: project old state with C*w
            u64 acc1 = mul2(c1r[0], sr[0]);
            acc1 = fma2(nc1i[0], si[0], acc1);
            #pragma unroll
            for (int p = 1; p < 4; p++) {
                acc1 = fma2(c1r[p], sr[p], acc1);
                acc1 = fma2(nc1i[p], si[p], acc1);
            }

            // state advance by two steps
            #pragma unroll
            for (int p = 0; p < 4; p++) {
                u64 vr = fma2(wr[p], ub0, ub1);
                u64 vi = mul2(wi[p], ub0);
                u64 t1 = fma2(nw2i[p], si[p], vr);
                u64 t2 = fma2(w2i[p], sr[p], vi);
                sr[p] = fma2(w2r[p], sr[p], t1);
                si[p] = fma2(w2r[p], si[p], t2);
            }

            // output 2: project new state with C
            u64 acc2 = mul2(cr[0], sr[0]);
            acc2 = fma2(nci[0], si[0], acc2);
            #pragma unroll
            for (int p = 1; p < 4; p++) {
                acc2 = fma2(cr[p], sr[p], acc2);
                acc2 = fma2(nci[p], si[p], acc2);
            }

            float l1, h1; upk2(acc1, l1, h1);
            float r1 = l1 + h1;
            r1 += __shfl_xor_sync(0xffffffffu, r1, 1);
            r1 += __shfl_xor_sync(0xffffffffu, r1, 2);
            float l2, h2; upk2(acc2, l2, h2);
            float r2 = l2 + h2;
            r2 += __shfl_xor_sync(0xffffffffu, r2, 1);
            r2 += __shfl_xor_sync(0xffffffffu, r2, 2);
            if (sub == 0) {
                buf[2 * i2][ch]     = fmaf(a0, u0, r1);
                buf[2 * i2 + 1][ch] = fmaf(dsk, u1, r2);
            }
        }
        __syncthreads();

        // GELU + fp16 writeback
        #pragma unroll
        for (int j = 0; j < 4; j++) {
            int idx = t + 256 * j;
            int ir = idx >> 4, c4 = idx & 15;
            int rr = (d == 0) ? (c * 64 + ir) : (LL - 1 - c * 64 - ir);
            float4 vv = *(float4*)&buf[ir][c4 * 4];
            vv.x = gelu_exact(vv.x); vv.y = gelu_exact(vv.y);
            vv.z = gelu_exact(vv.z); vv.w = gelu_exact(vv.w);
            __half2 h01 = __floats2half2_rn(vv.x, vv.y);
            __half2 h23 = __floats2half2_rn(vv.z, vv.w);
            size_t base = (mbase + rr) * DD + h0 + c4 * 4;
            uint2 uo;
            uo.x = *(uint32_t*)&h01; uo.y = *(uint32_t*)&h23;
            *(uint2*)&g_y[base] = uo;
        }
    }
}

// ---------------- kernel 3: fp16 mma GEMM, A-resident, fused GLU -------------
// CTA = 128 threads, one 64-row M tile. A (both dirs, K=256) = 64KB resident.
// 32 chunks g = (n0[4] x dir[2] x c[4]); B chunk 128N x 64K = 16KB through a
// 3-stage ring (48KB). Total smem 112KB -> 2 CTAs/SM.
static constexpr int A_BYTES   = 2 * 4 * 8192;             // 64KB (8 planes of 64x128B)
static constexpr int B_STAGE   = 16384;
static constexpr int SM_TOTAL  = A_BYTES + 3 * B_STAGE;    // 114688 = 112KB

__device__ __forceinline__ void load_A(uint32_t sb, size_t m0, int t)
{
    #pragma unroll
    for (int j = 0; j < 32; j++) {
        int idx = t + 128 * j;
        int plane = idx >> 9;             // dir*4 + c
        int r = (idx >> 3) & 63, seg = idx & 7;
        int dir = plane >> 2, c = plane & 3;
        const __half* src = g_y + ((size_t)dir * MM + m0 + r) * DD + c * 64 + seg * 8;
        cpa16(sb + plane * 8192 + swz(r * 128 + seg * 16), src);
    }
    asm volatile("cp.async.commit_group;" ::: "memory");
}

__device__ __forceinline__ void load_B(uint32_t bbase, int g, int t)
{
    const int n0 = g >> 3, dir = (g >> 2) & 1, c = g & 3;
    const __half* bsrc = g_wh + (size_t)dir * 2 * DD * DD
                       + (size_t)(n0 * 128) * DD + c * 64;
    #pragma unroll
    for (int j = 0; j < 8; j++) {
        int idx = t + 128 * j;
        int r = idx >> 3, seg = idx & 7;
        cpa16(bbase + swz(r * 128 + seg * 16), bsrc + (size_t)r * DD + seg * 8);
    }
    asm volatile("cp.async.commit_group;" ::: "memory");
}

__global__ __launch_bounds__(128, 2) void k_mm2(float* __restrict__ out)
{
    extern __shared__ __align__(1024) char smem[];
    uint32_t sb = smem_u32(smem);
    const uint32_t bB = sb + A_BYTES;
    const int t = threadIdx.x;
    const int lane = t & 31, w = t >> 5;
    const int mw = (w >> 1) * 32, nw = (w & 1) * 64;
    const size_t m0 = (size_t)blockIdx.x * 64;

    const uint32_t xorv = (lane & 7) * 16;
    uint32_t relA[2], relB[4];
    #pragma unroll
    for (int i = 0; i < 2; i++)
        relA[i] = (uint32_t)(mw + i * 16 + (lane & 15)) * 128;
    #pragma unroll
    for (int p = 0; p < 4; p++)
        relB[p] = (uint32_t)(nw + p * 16 + ((lane >> 4) << 3) + (lane & 7)) * 128;
    const uint32_t hsegA = (uint32_t)(lane >> 4);
    const uint32_t hsegB = (uint32_t)((lane >> 3) & 1);

    float acc[2][8][4];
    float oacc[2][8][2];
    #pragma unroll
    for (int i = 0; i < 2; i++)
        #pragma unroll
        for (int j = 0; j < 8; j++) {
            oacc[i][j][0] = 0.f; oacc[i][j][1] = 0.f;
            #pragma unroll
            for (int q = 0; q < 4; q++) acc[i][j][q] = 0.f;
        }

    load_A(sb, m0, t);
    load_B(bB + 0 * B_STAGE, 0, t);
    load_B(bB + 1 * B_STAGE, 1, t);

    for (int g = 0; g < 32; g++) {
        if (g < 31) asm volatile("cp.async.wait_group 1;" ::: "memory");
        else        asm volatile("cp.async.wait_group 0;" ::: "memory");
        __syncthreads();

        if (g + 2 < 32) load_B(bB + (uint32_t)((g + 2) % 3) * B_STAGE, g + 2, t);

        const int n0 = g >> 3, dir = (g >> 2) & 1, c = g & 3;
        const uint32_t abase = sb + (uint32_t)(dir * 4 + c) * 8192;
        const uint32_t bbase = bB + (uint32_t)(g % 3) * B_STAGE;

        #pragma unroll
        for (int kk = 0; kk < 4; kk++) {
            uint32_t soffA = (((uint32_t)(2 * kk) + hsegA) * 16) ^ xorv;
            uint32_t soffB = (((uint32_t)(2 * kk) + hsegB) * 16) ^ xorv;
            uint32_t afr[2][4], bfr[4][4];
            #pragma unroll
            for (int i = 0; i < 2; i++) LDM4(afr[i], abase + relA[i] + soffA);
            #pragma unroll
            for (int p = 0; p < 4; p++) LDM4(bfr[p], bbase + relB[p] + soffB);
            #pragma unroll
            for (int i = 0; i < 2; i++)
                #pragma unroll
                for (int j = 0; j < 8; j++)
                    MMA16816(acc[i][j], afr[i], bfr[j >> 1][(j & 1) * 2],
                             bfr[j >> 1][(j & 1) * 2 + 1]);
        }

        if (c == 3) {
            // GLU fold (cols interleaved: even=linear, odd=gate)
            #pragma unroll
            for (int i = 0; i < 2; i++)
                #pragma unroll
                for (int j = 0; j < 8; j++) {
                    int nl = n0 * 128 + nw + 8 * j + 2 * (lane & 3);
                    float bl = g_bias2[dir * 512 + nl];
                    float bg = g_bias2[dir * 512 + nl + 1];
                    oacc[i][j][0] += (acc[i][j][0] + bl) * sigm(acc[i][j][1] + bg);
                    oacc[i][j][1] += (acc[i][j][2] + bl) * sigm(acc[i][j][3] + bg);
                    #pragma unroll
                    for (int q = 0; q < 4; q++) acc[i][j][q] = 0.f;
                }
            if (dir == 1) {
                const int q = lane >> 2;
                const int chb = (n0 * 128 + nw) / 2 + (lane & 3);
                #pragma unroll
                for (int i = 0; i < 2; i++)
                    #pragma unroll
                    for (int s = 0; s < 2; s++) {
                        size_t m = m0 + mw + 16 * i + q + 8 * s;
                        float* dst = out + m * DD + chb;
                        #pragma unroll
                        for (int j = 0; j < 8; j++) dst[4 * j] = oacc[i][j][s];
                    }
                #pragma unroll
                for (int i = 0; i < 2; i++)
                    #pragma unroll
                    for (int j = 0; j < 8; j++) {
                        oacc[i][j][0] = 0.f; oacc[i][j][1] = 0.f;
                    }
            }
        }
    }
}

// ---------------- launch ------------------------------------------------------
extern "C" void kernel_launch(void* const* d_in, const int* in_sizes, int n_in,
                              void* d_out, int out_size)
{
    const float* x    = (const float*)d_in[0];
    const float* ld0  = (const float*)d_in[1];
    const float* cre0 = (const float*)d_in[2];
    const float* cim0 = (const float*)d_in[3];
    const float* lar0 = (const float*)d_in[4];
    const float* aim0 = (const float*)d_in[5];
    const float* ds0  = (const float*)d_in[6];
    const float* wg0  = (const float*)d_in[7];
    const float* bg0  = (const float*)d_in[8];
    const float* ld1  = (const float*)d_in[9];
    const float* cre1 = (const float*)d_in[10];
    const float* cim1 = (const float*)d_in[11];
    const float* lar1 = (const float*)d_in[12];
    const float* aim1 = (const float*)d_in[13];
    const float* ds1  = (const float*)d_in[14];
    const float* wg1  = (const float*)d_in[15];
    const float* bg1  = (const float*)d_in[16];
    float* out = (float*)d_out;

    static bool attr_done = false;
    if (!attr_done) {
        cudaFuncSetAttribute(k_mm2, cudaFuncAttributeMaxDynamicSharedMemorySize, SM_TOTAL);
        attr_done = true;
    }

    k_prep<<<(2 * DD * NN2 + 255) / 256, 256>>>(ld0, cre0, cim0, lar0, aim0,
                                                ld1, cre1, cim1, lar1, aim1);
    k_wt<<<(2 * 2 * DD * DD + 255) / 256, 256>>>(wg0, wg1, bg0, bg1);
    k_scan<<<dim3(DD / 64, BB, 2), 256>>>(x, ds0, ds1);
    k_mm2<<<MM / 64, 128, SM_TOTAL>>>(out);
}